// round 11
// baseline (speedup 1.0000x reference)
#include <cuda_runtime.h>
#include <cstdint>

#define N_Q   2048
#define N_P   256
#define EMB   512
#define NM    5
#define HID   64

// Scratch (allocation-free rule: __device__ globals)
__device__ float g_hqs[NM * N_Q * HID];          // hq + b1
__device__ float g_hps[NM * N_P * HID];          // hp

// ===========================================================================
// Kernel 1: bf16 HMMA GEMM with 3-term hi/lo split (R9, measured ~16.5us).
// ===========================================================================
#define SM_AHI 0
#define SM_ALO 16384
#define SM_WHI 32768
#define SM_WLO 40960

__device__ __forceinline__ uint32_t smem_u32(const void* p) {
    uint32_t a;
    asm("{ .reg .u64 t; cvta.to.shared.u64 t, %1; cvt.u32.u64 %0, t; }"
        : "=r"(a) : "l"(p));
    return a;
}

#define LDSM4(r, addr)                                                       \
    asm volatile("ldmatrix.sync.aligned.m8n8.x4.shared.b16 "                 \
                 "{%0,%1,%2,%3}, [%4];"                                      \
                 : "=r"((r)[0]), "=r"((r)[1]), "=r"((r)[2]), "=r"((r)[3])    \
                 : "r"(addr))

#define MMA16816(d, a, b0v, b1v)                                             \
    asm volatile("mma.sync.aligned.m16n8k16.row.col.f32.bf16.bf16.f32 "      \
                 "{%0,%1,%2,%3}, {%4,%5,%6,%7}, {%8,%9}, {%0,%1,%2,%3};"     \
                 : "+f"((d)[0]), "+f"((d)[1]), "+f"((d)[2]), "+f"((d)[3])    \
                 : "r"((a)[0]), "r"((a)[1]), "r"((a)[2]), "r"((a)[3]),       \
                   "r"(b0v), "r"(b1v))

__device__ __forceinline__ void split8(float4 a, float4 b, uint4& hi, uint4& lo) {
    asm("cvt.rn.bf16x2.f32 %0, %1, %2;" : "=r"(hi.x) : "f"(a.y), "f"(a.x));
    asm("cvt.rn.bf16x2.f32 %0, %1, %2;" : "=r"(hi.y) : "f"(a.w), "f"(a.z));
    asm("cvt.rn.bf16x2.f32 %0, %1, %2;" : "=r"(hi.z) : "f"(b.y), "f"(b.x));
    asm("cvt.rn.bf16x2.f32 %0, %1, %2;" : "=r"(hi.w) : "f"(b.w), "f"(b.z));
    float h0 = __uint_as_float(hi.x << 16), h1 = __uint_as_float(hi.x & 0xFFFF0000u);
    float h2 = __uint_as_float(hi.y << 16), h3 = __uint_as_float(hi.y & 0xFFFF0000u);
    float h4 = __uint_as_float(hi.z << 16), h5 = __uint_as_float(hi.z & 0xFFFF0000u);
    float h6 = __uint_as_float(hi.w << 16), h7 = __uint_as_float(hi.w & 0xFFFF0000u);
    asm("cvt.rn.bf16x2.f32 %0, %1, %2;" : "=r"(lo.x) : "f"(a.y - h1), "f"(a.x - h0));
    asm("cvt.rn.bf16x2.f32 %0, %1, %2;" : "=r"(lo.y) : "f"(a.w - h3), "f"(a.z - h2));
    asm("cvt.rn.bf16x2.f32 %0, %1, %2;" : "=r"(lo.z) : "f"(b.y - h5), "f"(b.x - h4));
    asm("cvt.rn.bf16x2.f32 %0, %1, %2;" : "=r"(lo.w) : "f"(b.w - h7), "f"(b.z - h6));
}

__global__ __launch_bounds__(128) void gemm_mma_kernel(
    const float* __restrict__ Q, const float* __restrict__ P,
    const float* __restrict__ W1, const float* __restrict__ b1)
{
    __shared__ __align__(128) char smem[49152];
    const uint32_t sb = smem_u32(smem);

    const int tid  = threadIdx.x;
    const int wid  = tid >> 5;
    const int lane = tid & 31;

    const int m  = blockIdx.y;
    const int rt = blockIdx.x;
    const bool is_q = rt < (N_Q / 64);

    const float* src;
    int row0;
    float* dst;
    if (is_q) {
        src = Q;  row0 = rt * 64;
        dst = g_hqs + (size_t)(m * N_Q + row0) * HID;
    } else {
        src = P;  row0 = (rt - N_Q / 64) * 64;
        dst = g_hps + (size_t)(m * N_P + row0) * HID;
    }
    const float* Sb = src + (size_t)row0 * EMB;
    const float* Wb = W1 + (size_t)m * HID * (2 * EMB) + (is_q ? 0 : EMB);

    const int st_row = tid >> 3;
    const int st_kg  = tid & 7;

    float4 pa[8], pw[8];
    auto ldg_chunk = [&](int c) {
        const int kt = c * 64;
        #pragma unroll
        for (int i = 0; i < 4; i++) {
            int row = st_row + i * 16;
            const float* g  = Sb + (size_t)row * EMB + kt + st_kg * 8;
            const float* gw = Wb + (size_t)row * (2 * EMB) + kt + st_kg * 8;
            pa[2 * i]     = *(const float4*)g;
            pa[2 * i + 1] = *(const float4*)(g + 4);
            pw[2 * i]     = *(const float4*)gw;
            pw[2 * i + 1] = *(const float4*)(gw + 4);
        }
    };
    auto sts_chunk = [&]() {
        #pragma unroll
        for (int i = 0; i < 4; i++) {
            int row = st_row + i * 16;
            uint32_t off = (uint32_t)(row * 128 + ((st_kg ^ (row & 7)) << 4));
            uint4 hi, lo;
            split8(pa[2 * i], pa[2 * i + 1], hi, lo);
            *(uint4*)(smem + SM_AHI + off) = hi;
            *(uint4*)(smem + SM_ALO + off) = lo;
            split8(pw[2 * i], pw[2 * i + 1], hi, lo);
            *(uint4*)(smem + SM_WHI + off) = hi;
            *(uint4*)(smem + SM_WLO + off) = lo;
        }
    };

    const int rA    = wid * 16 + (lane & 15);
    const int rx7A  = rA & 7;
    const int kselA = lane >> 4;
    const int rB_loc  = ((lane >> 4) & 1) * 8 + (lane & 7);
    const int kgB_add = (lane >> 3) & 1;

    float acc[8][4] = {};

    ldg_chunk(0);

    for (int c = 0; c < 8; c++) {
        sts_chunk();
        __syncthreads();
        if (c < 7) ldg_chunk(c + 1);

        #pragma unroll
        for (int ks = 0; ks < 4; ks++) {
            const int kgA = ks * 2 + kselA;
            const uint32_t aoff = (uint32_t)(rA * 128 + ((kgA ^ rx7A) << 4));
            uint32_t ahi[4], alo[4];
            LDSM4(ahi, sb + SM_AHI + aoff);
            LDSM4(alo, sb + SM_ALO + aoff);

            #pragma unroll
            for (int j = 0; j < 4; j++) {
                const int rB  = j * 16 + rB_loc;
                const int kgB = ks * 2 + kgB_add;
                const uint32_t boff = (uint32_t)(rB * 128 + ((kgB ^ (rB & 7)) << 4));
                uint32_t bhi[4], blo[4];
                LDSM4(bhi, sb + SM_WHI + boff);
                LDSM4(blo, sb + SM_WLO + boff);

                MMA16816(acc[2 * j],     ahi, bhi[0], bhi[1]);
                MMA16816(acc[2 * j],     ahi, blo[0], blo[1]);
                MMA16816(acc[2 * j],     alo, bhi[0], bhi[1]);
                MMA16816(acc[2 * j + 1], ahi, bhi[2], bhi[3]);
                MMA16816(acc[2 * j + 1], ahi, blo[2], blo[3]);
                MMA16816(acc[2 * j + 1], alo, bhi[2], bhi[3]);
            }
        }
        __syncthreads();
    }

    const int er = lane >> 2;
    const int ec = (lane & 3) * 2;
    float* d0 = dst + (size_t)(wid * 16 + er) * HID;
    float* d1 = dst + (size_t)(wid * 16 + er + 8) * HID;
    #pragma unroll
    for (int nf = 0; nf < 8; nf++) {
        float bx = 0.f, by = 0.f;
        if (is_q) {
            float2 bv = *(const float2*)(b1 + m * HID + nf * 8 + ec);
            bx = bv.x; by = bv.y;
        }
        *(float2*)(d0 + nf * 8 + ec) = make_float2(acc[nf][0] + bx, acc[nf][1] + by);
        *(float2*)(d1 + nf * 8 + ec) = make_float2(acc[nf][2] + bx, acc[nf][3] + by);
    }
}

// ===========================================================================
// Kernel 2: fused relu-combine + h-reduction + ensemble stats.
// Tile: 64q x 64p, 256 threads, 4x4 outputs/thread (LDS/elem -36% vs R9).
// Triple-buffer cp.async; branch-free packed relu via abs trick (R4-proven):
//   relu(s)*w == (s + |s|) * (w * 0.5)  -> add2 + and.b64 + add2 + fma2
// grid = (32, 4) = 128 blocks.
// ===========================================================================
#define BQ 64
#define BP 64
#define BUF_FLOATS ((BQ + BP) * HID)              // 8192 floats = 32 KB
#define SMEM_FLOATS (3 * BUF_FLOATS + NM * HID + 8)
#define SMEM_BYTES  (SMEM_FLOATS * 4)

#define RELU_FMA2(acc, x2, y2, w2)                                    \
    asm("{\n\t"                                                       \
        ".reg .b64 s, a;\n\t"                                         \
        "add.rn.f32x2 s, %1, %2;\n\t"                                 \
        "and.b64 a, s, 0x7FFFFFFF7FFFFFFF;\n\t"                       \
        "add.rn.f32x2 s, s, a;\n\t"                                   \
        "fma.rn.f32x2 %0, s, %3, %0;\n\t"                             \
        "}"                                                           \
        : "+l"(acc) : "l"(x2), "l"(y2), "l"(w2))

__device__ __forceinline__ void cpa16(void* smem_ptr, const void* gptr) {
    uint32_t s = (uint32_t)__cvta_generic_to_shared(smem_ptr);
    asm volatile("cp.async.cg.shared.global [%0], [%1], 16;" :: "r"(s), "l"(gptr));
}

__global__ __launch_bounds__(256) void final_kernel(
    const float* __restrict__ W2, const float* __restrict__ b2,
    float* __restrict__ out)
{
    extern __shared__ float smem_f[];
    float* s_w2 = smem_f + 3 * BUF_FLOATS;
    float* s_b2 = s_w2 + NM * HID;

    const int tid = threadIdx.x;
    const int q0  = blockIdx.x * BQ;
    const int p0  = blockIdx.y * BP;
    const int tyq = tid >> 4;   // 0..15 -> q rows tyq*4 .. +3
    const int txp = tid & 15;   // 0..15 -> p rows txp*4 .. +3

    for (int i = tid; i < NM * HID; i += 256) s_w2[i] = 0.5f * W2[i];
    if (tid < NM) s_b2[tid] = b2[tid];

    // stage one model's tiles: x: 64x16 f4 = 1024, y: 64x16 f4 = 1024 -> 8/thread
    auto stage = [&](int m, int b) {
        float* base = smem_f + b * BUF_FLOATS;
        #pragma unroll
        for (int k = 0; k < 8; k++) {
            int idx = tid + k * 256;
            const float* g;
            float* s;
            if (idx < 1024) {
                int row = idx >> 4;
                int c4  = idx & 15;
                int sc  = ((c4 ^ (row >> 2)) & 15) * 4;
                g = g_hqs + ((size_t)(m * N_Q + q0 + row)) * HID + c4 * 4;
                s = base + row * HID + sc;
            } else {
                int t   = idx - 1024;
                int row = t >> 4;
                int c4  = t & 15;
                int sc  = ((c4 ^ (row >> 2)) & 15) * 4;
                g = g_hps + ((size_t)(m * N_P + p0 + row)) * HID + c4 * 4;
                s = base + (BQ + row) * HID + sc;
            }
            cpa16(s, g);
        }
        asm volatile("cp.async.commit_group;");
    };

    stage(0, 0);
    stage(1, 1);

    float sum[4][4] = {};
    float sq [4][4] = {};

    for (int m = 0; m < NM; m++) {
        if (m + 2 < NM) {
            stage(m + 2, (m + 2) % 3);
            asm volatile("cp.async.wait_group 2;");
        } else if (m + 1 < NM) {
            asm volatile("cp.async.wait_group 1;");
        } else {
            asm volatile("cp.async.wait_group 0;");
        }
        __syncthreads();

        const float* bx   = smem_f + (m % 3) * BUF_FLOATS;
        const float* xrow = bx + (tyq * 4) * HID;
        const float* yrow = bx + (BQ + txp * 4) * HID;
        const float* wrow = s_w2 + m * HID;

        unsigned long long acc[4][4] = {};

        #pragma unroll 4
        for (int c4 = 0; c4 < 16; c4++) {
            int cx = ((c4 ^ tyq) & 15) * 4;
            int cy = ((c4 ^ txp) & 15) * 4;
            ulonglong2 X[4], Y[4];
            #pragma unroll
            for (int i = 0; i < 4; i++)
                X[i] = *(const ulonglong2*)(xrow + i * HID + cx);
            #pragma unroll
            for (int j = 0; j < 4; j++)
                Y[j] = *(const ulonglong2*)(yrow + j * HID + cy);
            ulonglong2 Wv = *(const ulonglong2*)(wrow + c4 * 4);

            #pragma unroll
            for (int i = 0; i < 4; i++)
                #pragma unroll
                for (int j = 0; j < 4; j++) {
                    RELU_FMA2(acc[i][j], X[i].x, Y[j].x, Wv.x);
                    RELU_FMA2(acc[i][j], X[i].y, Y[j].y, Wv.y);
                }
        }

        float bb = s_b2[m];
        #pragma unroll
        for (int i = 0; i < 4; i++)
            #pragma unroll
            for (int j = 0; j < 4; j++) {
                unsigned long long a = acc[i][j];
                float lo = __uint_as_float((unsigned)(a & 0xFFFFFFFFull));
                float hi = __uint_as_float((unsigned)(a >> 32));
                float o  = lo + hi + bb;
                sum[i][j] += o;
                sq [i][j] += o * o;
            }

        __syncthreads();
    }

    #pragma unroll
    for (int i = 0; i < 4; i++)
        #pragma unroll
        for (int j = 0; j < 4; j++) {
            float mean = sum[i][j] * 0.2f;
            float var  = fmaxf(sq[i][j] - 5.0f * mean * mean, 0.0f) * 0.25f; // ddof=1
            float r    = mean * expf(-sqrtf(var));
            int q = q0 + tyq * 4 + i;
            int p = p0 + txp * 4 + j;
            out[(size_t)q * N_P + p] = r;
        }
}

// ---------------------------------------------------------------------------
extern "C" void kernel_launch(void* const* d_in, const int* in_sizes, int n_in,
                              void* d_out, int out_size)
{
    const float* Q  = (const float*)d_in[0];
    const float* P  = (const float*)d_in[1];
    const float* W1 = (const float*)d_in[2];
    const float* b1 = (const float*)d_in[3];
    const float* W2 = (const float*)d_in[4];
    const float* b2 = (const float*)d_in[5];
    float* out = (float*)d_out;

    dim3 g1(N_Q / 64 + N_P / 64, NM);             // (36, 5) = 180 blocks
    gemm_mma_kernel<<<g1, 128>>>(Q, P, W1, b1);

    cudaFuncSetAttribute(final_kernel,
                         cudaFuncAttributeMaxDynamicSharedMemorySize, SMEM_BYTES);
    dim3 g3(N_Q / BQ, N_P / BP);                  // (32, 4) = 128 blocks
    final_kernel<<<g3, 256, SMEM_BYTES>>>(W2, b2, out);
}

// round 12
// speedup vs baseline: 1.0061x; 1.0061x over previous
#include <cuda_runtime.h>
#include <cstdint>

#define N_Q   2048
#define N_P   256
#define EMB   512
#define NM    5
#define HID   64

// Scratch (allocation-free rule: __device__ globals)
__device__ float g_hqs[NM * N_Q * HID];          // hq + b1
__device__ float g_hps[NM * N_P * HID];          // hp

// ===========================================================================
// Kernel 1: bf16 HMMA GEMM with 3-term hi/lo split (R9, measured ~16.5us).
// ===========================================================================
#define SM_AHI 0
#define SM_ALO 16384
#define SM_WHI 32768
#define SM_WLO 40960

__device__ __forceinline__ uint32_t smem_u32(const void* p) {
    uint32_t a;
    asm("{ .reg .u64 t; cvta.to.shared.u64 t, %1; cvt.u32.u64 %0, t; }"
        : "=r"(a) : "l"(p));
    return a;
}

#define LDSM4(r, addr)                                                       \
    asm volatile("ldmatrix.sync.aligned.m8n8.x4.shared.b16 "                 \
                 "{%0,%1,%2,%3}, [%4];"                                      \
                 : "=r"((r)[0]), "=r"((r)[1]), "=r"((r)[2]), "=r"((r)[3])    \
                 : "r"(addr))

#define MMA16816(d, a, b0v, b1v)                                             \
    asm volatile("mma.sync.aligned.m16n8k16.row.col.f32.bf16.bf16.f32 "      \
                 "{%0,%1,%2,%3}, {%4,%5,%6,%7}, {%8,%9}, {%0,%1,%2,%3};"     \
                 : "+f"((d)[0]), "+f"((d)[1]), "+f"((d)[2]), "+f"((d)[3])    \
                 : "r"((a)[0]), "r"((a)[1]), "r"((a)[2]), "r"((a)[3]),       \
                   "r"(b0v), "r"(b1v))

__device__ __forceinline__ void split8(float4 a, float4 b, uint4& hi, uint4& lo) {
    asm("cvt.rn.bf16x2.f32 %0, %1, %2;" : "=r"(hi.x) : "f"(a.y), "f"(a.x));
    asm("cvt.rn.bf16x2.f32 %0, %1, %2;" : "=r"(hi.y) : "f"(a.w), "f"(a.z));
    asm("cvt.rn.bf16x2.f32 %0, %1, %2;" : "=r"(hi.z) : "f"(b.y), "f"(b.x));
    asm("cvt.rn.bf16x2.f32 %0, %1, %2;" : "=r"(hi.w) : "f"(b.w), "f"(b.z));
    float h0 = __uint_as_float(hi.x << 16), h1 = __uint_as_float(hi.x & 0xFFFF0000u);
    float h2 = __uint_as_float(hi.y << 16), h3 = __uint_as_float(hi.y & 0xFFFF0000u);
    float h4 = __uint_as_float(hi.z << 16), h5 = __uint_as_float(hi.z & 0xFFFF0000u);
    float h6 = __uint_as_float(hi.w << 16), h7 = __uint_as_float(hi.w & 0xFFFF0000u);
    asm("cvt.rn.bf16x2.f32 %0, %1, %2;" : "=r"(lo.x) : "f"(a.y - h1), "f"(a.x - h0));
    asm("cvt.rn.bf16x2.f32 %0, %1, %2;" : "=r"(lo.y) : "f"(a.w - h3), "f"(a.z - h2));
    asm("cvt.rn.bf16x2.f32 %0, %1, %2;" : "=r"(lo.z) : "f"(b.y - h5), "f"(b.x - h4));
    asm("cvt.rn.bf16x2.f32 %0, %1, %2;" : "=r"(lo.w) : "f"(b.w - h7), "f"(b.z - h6));
}

__global__ __launch_bounds__(128) void gemm_mma_kernel(
    const float* __restrict__ Q, const float* __restrict__ P,
    const float* __restrict__ W1, const float* __restrict__ b1)
{
    __shared__ __align__(128) char smem[49152];
    const uint32_t sb = smem_u32(smem);

    const int tid  = threadIdx.x;
    const int wid  = tid >> 5;
    const int lane = tid & 31;

    const int m  = blockIdx.y;
    const int rt = blockIdx.x;
    const bool is_q = rt < (N_Q / 64);

    const float* src;
    int row0;
    float* dst;
    if (is_q) {
        src = Q;  row0 = rt * 64;
        dst = g_hqs + (size_t)(m * N_Q + row0) * HID;
    } else {
        src = P;  row0 = (rt - N_Q / 64) * 64;
        dst = g_hps + (size_t)(m * N_P + row0) * HID;
    }
    const float* Sb = src + (size_t)row0 * EMB;
    const float* Wb = W1 + (size_t)m * HID * (2 * EMB) + (is_q ? 0 : EMB);

    const int st_row = tid >> 3;
    const int st_kg  = tid & 7;

    float4 pa[8], pw[8];
    auto ldg_chunk = [&](int c) {
        const int kt = c * 64;
        #pragma unroll
        for (int i = 0; i < 4; i++) {
            int row = st_row + i * 16;
            const float* g  = Sb + (size_t)row * EMB + kt + st_kg * 8;
            const float* gw = Wb + (size_t)row * (2 * EMB) + kt + st_kg * 8;
            pa[2 * i]     = *(const float4*)g;
            pa[2 * i + 1] = *(const float4*)(g + 4);
            pw[2 * i]     = *(const float4*)gw;
            pw[2 * i + 1] = *(const float4*)(gw + 4);
        }
    };
    auto sts_chunk = [&]() {
        #pragma unroll
        for (int i = 0; i < 4; i++) {
            int row = st_row + i * 16;
            uint32_t off = (uint32_t)(row * 128 + ((st_kg ^ (row & 7)) << 4));
            uint4 hi, lo;
            split8(pa[2 * i], pa[2 * i + 1], hi, lo);
            *(uint4*)(smem + SM_AHI + off) = hi;
            *(uint4*)(smem + SM_ALO + off) = lo;
            split8(pw[2 * i], pw[2 * i + 1], hi, lo);
            *(uint4*)(smem + SM_WHI + off) = hi;
            *(uint4*)(smem + SM_WLO + off) = lo;
        }
    };

    const int rA    = wid * 16 + (lane & 15);
    const int rx7A  = rA & 7;
    const int kselA = lane >> 4;
    const int rB_loc  = ((lane >> 4) & 1) * 8 + (lane & 7);
    const int kgB_add = (lane >> 3) & 1;

    float acc[8][4] = {};

    ldg_chunk(0);

    for (int c = 0; c < 8; c++) {
        sts_chunk();
        __syncthreads();
        if (c < 7) ldg_chunk(c + 1);

        #pragma unroll
        for (int ks = 0; ks < 4; ks++) {
            const int kgA = ks * 2 + kselA;
            const uint32_t aoff = (uint32_t)(rA * 128 + ((kgA ^ rx7A) << 4));
            uint32_t ahi[4], alo[4];
            LDSM4(ahi, sb + SM_AHI + aoff);
            LDSM4(alo, sb + SM_ALO + aoff);

            #pragma unroll
            for (int j = 0; j < 4; j++) {
                const int rB  = j * 16 + rB_loc;
                const int kgB = ks * 2 + kgB_add;
                const uint32_t boff = (uint32_t)(rB * 128 + ((kgB ^ (rB & 7)) << 4));
                uint32_t bhi[4], blo[4];
                LDSM4(bhi, sb + SM_WHI + boff);
                LDSM4(blo, sb + SM_WLO + boff);

                MMA16816(acc[2 * j],     ahi, bhi[0], bhi[1]);
                MMA16816(acc[2 * j],     ahi, blo[0], blo[1]);
                MMA16816(acc[2 * j],     alo, bhi[0], bhi[1]);
                MMA16816(acc[2 * j + 1], ahi, bhi[2], bhi[3]);
                MMA16816(acc[2 * j + 1], ahi, blo[2], blo[3]);
                MMA16816(acc[2 * j + 1], alo, bhi[2], bhi[3]);
            }
        }
        __syncthreads();
    }

    const int er = lane >> 2;
    const int ec = (lane & 3) * 2;
    float* d0 = dst + (size_t)(wid * 16 + er) * HID;
    float* d1 = dst + (size_t)(wid * 16 + er + 8) * HID;
    #pragma unroll
    for (int nf = 0; nf < 8; nf++) {
        float bx = 0.f, by = 0.f;
        if (is_q) {
            float2 bv = *(const float2*)(b1 + m * HID + nf * 8 + ec);
            bx = bv.x; by = bv.y;
        }
        *(float2*)(d0 + nf * 8 + ec) = make_float2(acc[nf][0] + bx, acc[nf][1] + by);
        *(float2*)(d1 + nf * 8 + ec) = make_float2(acc[nf][2] + bx, acc[nf][3] + by);
    }
}

// ===========================================================================
// Kernel 2: fused relu-combine + h-reduction + ensemble stats.
// Tile: 32q x 16p per ONE-WARP block (32 thr), 4x4 outputs/thread.
// grid = (64, 16) = 1024 blocks -> 6.9 blocks/SM, 8 independent
// warps co-resident per SM (25.3 KB smem each), 1.2% fill quantization.
// Double-buffered cp.async over m; abs-trick packed relu (3 fma + 1 alu / 2).
// ===========================================================================
#define BQ 32
#define BP 16
#define BUF_FLOATS ((BQ + BP) * HID)              // 3072 floats = 12 KB
#define SMEM_FLOATS (2 * BUF_FLOATS + NM * HID + 8)
#define SMEM_BYTES  (SMEM_FLOATS * 4)

#define RELU_FMA2(acc, x2, y2, w2)                                    \
    asm("{\n\t"                                                       \
        ".reg .b64 s, a;\n\t"                                         \
        "add.rn.f32x2 s, %1, %2;\n\t"                                 \
        "and.b64 a, s, 0x7FFFFFFF7FFFFFFF;\n\t"                       \
        "add.rn.f32x2 s, s, a;\n\t"                                   \
        "fma.rn.f32x2 %0, s, %3, %0;\n\t"                             \
        "}"                                                           \
        : "+l"(acc) : "l"(x2), "l"(y2), "l"(w2))

__device__ __forceinline__ void cpa16(void* smem_ptr, const void* gptr) {
    uint32_t s = (uint32_t)__cvta_generic_to_shared(smem_ptr);
    asm volatile("cp.async.cg.shared.global [%0], [%1], 16;" :: "r"(s), "l"(gptr));
}

__global__ __launch_bounds__(32) void final_kernel(
    const float* __restrict__ W2, const float* __restrict__ b2,
    float* __restrict__ out)
{
    extern __shared__ float smem_f[];
    float* s_w2 = smem_f + 2 * BUF_FLOATS;
    float* s_b2 = s_w2 + NM * HID;

    const int tid = threadIdx.x;        // 0..31
    const int q0  = blockIdx.x * BQ;
    const int p0  = blockIdx.y * BP;
    const int tyq = tid >> 2;           // 0..7  -> q rows tyq*4 .. +3
    const int txp = tid & 3;            // 0..3  -> p rows txp*4 .. +3

    // W2 prescaled by 0.5 for the abs-trick; b2 plain.
    #pragma unroll
    for (int i = tid; i < NM * HID; i += 32) s_w2[i] = 0.5f * W2[i];
    if (tid < NM) s_b2[tid] = b2[tid];

    // stage one model: x tile 32x16 f4 = 512, y tile 16x16 f4 = 256 -> 24/thread
    auto stage = [&](int m, int b) {
        float* base = smem_f + b * BUF_FLOATS;
        #pragma unroll
        for (int k = 0; k < 24; k++) {
            int idx = tid + k * 32;     // 0..767
            const float* g;
            float* s;
            if (idx < 512) {
                int row = idx >> 4;     // 0..31
                int c4  = idx & 15;
                int sc  = ((c4 ^ (row >> 2)) & 15) * 4;
                g = g_hqs + ((size_t)(m * N_Q + q0 + row)) * HID + c4 * 4;
                s = base + row * HID + sc;
            } else {
                int t   = idx - 512;
                int row = t >> 4;       // 0..15
                int c4  = t & 15;
                int sc  = ((c4 ^ (row >> 2)) & 15) * 4;
                g = g_hps + ((size_t)(m * N_P + p0 + row)) * HID + c4 * 4;
                s = base + (BQ + row) * HID + sc;
            }
            cpa16(s, g);
        }
        asm volatile("cp.async.commit_group;");
    };

    stage(0, 0);
    stage(1, 1);

    float sum[4][4] = {};
    float sq [4][4] = {};

    for (int m = 0; m < NM; m++) {
        if (m < NM - 1) {
            asm volatile("cp.async.wait_group 1;");
        } else {
            asm volatile("cp.async.wait_group 0;");
        }
        __syncwarp();

        const float* bx   = smem_f + (m & 1) * BUF_FLOATS;
        const float* xrow = bx + (tyq * 4) * HID;
        const float* yrow = bx + (BQ + txp * 4) * HID;
        const float* wrow = s_w2 + m * HID;

        unsigned long long acc[4][4] = {};

        #pragma unroll 4
        for (int c4 = 0; c4 < 16; c4++) {
            int cx = ((c4 ^ tyq) & 15) * 4;
            int cy = ((c4 ^ txp) & 15) * 4;
            ulonglong2 X[4], Y[4];
            #pragma unroll
            for (int i = 0; i < 4; i++)
                X[i] = *(const ulonglong2*)(xrow + i * HID + cx);
            #pragma unroll
            for (int j = 0; j < 4; j++)
                Y[j] = *(const ulonglong2*)(yrow + j * HID + cy);
            ulonglong2 Wv = *(const ulonglong2*)(wrow + c4 * 4);

            #pragma unroll
            for (int i = 0; i < 4; i++)
                #pragma unroll
                for (int j = 0; j < 4; j++) {
                    RELU_FMA2(acc[i][j], X[i].x, Y[j].x, Wv.x);
                    RELU_FMA2(acc[i][j], X[i].y, Y[j].y, Wv.y);
                }
        }

        float bb = s_b2[m];
        #pragma unroll
        for (int i = 0; i < 4; i++)
            #pragma unroll
            for (int j = 0; j < 4; j++) {
                unsigned long long a = acc[i][j];
                float lo = __uint_as_float((unsigned)(a & 0xFFFFFFFFull));
                float hi = __uint_as_float((unsigned)(a >> 32));
                float o  = lo + hi + bb;
                sum[i][j] += o;
                sq [i][j] += o * o;
            }

        __syncwarp();                   // all lanes done reading buf m&1
        if (m + 2 < NM) stage(m + 2, m & 1);
    }

    #pragma unroll
    for (int i = 0; i < 4; i++) {
        float4 r4;
        float* rp = (float*)&r4;
        #pragma unroll
        for (int j = 0; j < 4; j++) {
            float mean = sum[i][j] * 0.2f;
            float var  = fmaxf(sq[i][j] - 5.0f * mean * mean, 0.0f) * 0.25f; // ddof=1
            rp[j] = mean * expf(-sqrtf(var));
        }
        int q = q0 + tyq * 4 + i;
        *(float4*)(out + (size_t)q * N_P + p0 + txp * 4) = r4;
    }
}

// ---------------------------------------------------------------------------
extern "C" void kernel_launch(void* const* d_in, const int* in_sizes, int n_in,
                              void* d_out, int out_size)
{
    const float* Q  = (const float*)d_in[0];
    const float* P  = (const float*)d_in[1];
    const float* W1 = (const float*)d_in[2];
    const float* b1 = (const float*)d_in[3];
    const float* W2 = (const float*)d_in[4];
    const float* b2 = (const float*)d_in[5];
    float* out = (float*)d_out;

    dim3 g1(N_Q / 64 + N_P / 64, NM);             // (36, 5) = 180 blocks
    gemm_mma_kernel<<<g1, 128>>>(Q, P, W1, b1);

    cudaFuncSetAttribute(final_kernel,
                         cudaFuncAttributeMaxDynamicSharedMemorySize, SMEM_BYTES);
    dim3 g3(N_Q / BQ, N_P / BP);                  // (64, 16) = 1024 blocks
    final_kernel<<<g3, 32, SMEM_BYTES>>>(W2, b2, out);
}

// round 13
// speedup vs baseline: 1.1008x; 1.0942x over previous
#include <cuda_runtime.h>
#include <cstdint>

#define N_Q   2048
#define N_P   256
#define EMB   512
#define NM    5
#define HID   64

// Scratch (allocation-free rule: __device__ globals)
__device__ float g_hqs[NM * N_Q * HID];          // hq + b1
__device__ float g_hps[NM * N_P * HID];          // hp
__device__ float g_rsq[NM * N_Q];                // sum_h (hq+b1)*w2/2
__device__ float g_rsp[NM * N_P];                // sum_h hp*w2/2

// ===========================================================================
// Kernel 1: bf16 HMMA GEMM with 3-term hi/lo split (R9 core, measured).
// Epilogue additionally computes per-row dot with w2/2 -> g_rsq/g_rsp.
// ===========================================================================
#define SM_AHI 0
#define SM_ALO 16384
#define SM_WHI 32768
#define SM_WLO 40960

__device__ __forceinline__ uint32_t smem_u32(const void* p) {
    uint32_t a;
    asm("{ .reg .u64 t; cvta.to.shared.u64 t, %1; cvt.u32.u64 %0, t; }"
        : "=r"(a) : "l"(p));
    return a;
}

#define LDSM4(r, addr)                                                       \
    asm volatile("ldmatrix.sync.aligned.m8n8.x4.shared.b16 "                 \
                 "{%0,%1,%2,%3}, [%4];"                                      \
                 : "=r"((r)[0]), "=r"((r)[1]), "=r"((r)[2]), "=r"((r)[3])    \
                 : "r"(addr))

#define MMA16816(d, a, b0v, b1v)                                             \
    asm volatile("mma.sync.aligned.m16n8k16.row.col.f32.bf16.bf16.f32 "      \
                 "{%0,%1,%2,%3}, {%4,%5,%6,%7}, {%8,%9}, {%0,%1,%2,%3};"     \
                 : "+f"((d)[0]), "+f"((d)[1]), "+f"((d)[2]), "+f"((d)[3])    \
                 : "r"((a)[0]), "r"((a)[1]), "r"((a)[2]), "r"((a)[3]),       \
                   "r"(b0v), "r"(b1v))

__device__ __forceinline__ void split8(float4 a, float4 b, uint4& hi, uint4& lo) {
    asm("cvt.rn.bf16x2.f32 %0, %1, %2;" : "=r"(hi.x) : "f"(a.y), "f"(a.x));
    asm("cvt.rn.bf16x2.f32 %0, %1, %2;" : "=r"(hi.y) : "f"(a.w), "f"(a.z));
    asm("cvt.rn.bf16x2.f32 %0, %1, %2;" : "=r"(hi.z) : "f"(b.y), "f"(b.x));
    asm("cvt.rn.bf16x2.f32 %0, %1, %2;" : "=r"(hi.w) : "f"(b.w), "f"(b.z));
    float h0 = __uint_as_float(hi.x << 16), h1 = __uint_as_float(hi.x & 0xFFFF0000u);
    float h2 = __uint_as_float(hi.y << 16), h3 = __uint_as_float(hi.y & 0xFFFF0000u);
    float h4 = __uint_as_float(hi.z << 16), h5 = __uint_as_float(hi.z & 0xFFFF0000u);
    float h6 = __uint_as_float(hi.w << 16), h7 = __uint_as_float(hi.w & 0xFFFF0000u);
    asm("cvt.rn.bf16x2.f32 %0, %1, %2;" : "=r"(lo.x) : "f"(a.y - h1), "f"(a.x - h0));
    asm("cvt.rn.bf16x2.f32 %0, %1, %2;" : "=r"(lo.y) : "f"(a.w - h3), "f"(a.z - h2));
    asm("cvt.rn.bf16x2.f32 %0, %1, %2;" : "=r"(lo.z) : "f"(b.y - h5), "f"(b.x - h4));
    asm("cvt.rn.bf16x2.f32 %0, %1, %2;" : "=r"(lo.w) : "f"(b.w - h7), "f"(b.z - h6));
}

__global__ __launch_bounds__(128) void gemm_mma_kernel(
    const float* __restrict__ Q, const float* __restrict__ P,
    const float* __restrict__ W1, const float* __restrict__ b1,
    const float* __restrict__ W2)
{
    __shared__ __align__(128) char smem[49152];
    const uint32_t sb = smem_u32(smem);

    const int tid  = threadIdx.x;
    const int wid  = tid >> 5;
    const int lane = tid & 31;

    const int m  = blockIdx.y;
    const int rt = blockIdx.x;
    const bool is_q = rt < (N_Q / 64);

    const float* src;
    int row0;
    float* dst;
    float* rs_dst;
    if (is_q) {
        src = Q;  row0 = rt * 64;
        dst = g_hqs + (size_t)(m * N_Q + row0) * HID;
        rs_dst = g_rsq + m * N_Q + row0;
    } else {
        src = P;  row0 = (rt - N_Q / 64) * 64;
        dst = g_hps + (size_t)(m * N_P + row0) * HID;
        rs_dst = g_rsp + m * N_P + row0;
    }
    const float* Sb = src + (size_t)row0 * EMB;
    const float* Wb = W1 + (size_t)m * HID * (2 * EMB) + (is_q ? 0 : EMB);

    const int st_row = tid >> 3;
    const int st_kg  = tid & 7;

    float4 pa[8], pw[8];
    auto ldg_chunk = [&](int c) {
        const int kt = c * 64;
        #pragma unroll
        for (int i = 0; i < 4; i++) {
            int row = st_row + i * 16;
            const float* g  = Sb + (size_t)row * EMB + kt + st_kg * 8;
            const float* gw = Wb + (size_t)row * (2 * EMB) + kt + st_kg * 8;
            pa[2 * i]     = *(const float4*)g;
            pa[2 * i + 1] = *(const float4*)(g + 4);
            pw[2 * i]     = *(const float4*)gw;
            pw[2 * i + 1] = *(const float4*)(gw + 4);
        }
    };
    auto sts_chunk = [&]() {
        #pragma unroll
        for (int i = 0; i < 4; i++) {
            int row = st_row + i * 16;
            uint32_t off = (uint32_t)(row * 128 + ((st_kg ^ (row & 7)) << 4));
            uint4 hi, lo;
            split8(pa[2 * i], pa[2 * i + 1], hi, lo);
            *(uint4*)(smem + SM_AHI + off) = hi;
            *(uint4*)(smem + SM_ALO + off) = lo;
            split8(pw[2 * i], pw[2 * i + 1], hi, lo);
            *(uint4*)(smem + SM_WHI + off) = hi;
            *(uint4*)(smem + SM_WLO + off) = lo;
        }
    };

    const int rA    = wid * 16 + (lane & 15);
    const int rx7A  = rA & 7;
    const int kselA = lane >> 4;
    const int rB_loc  = ((lane >> 4) & 1) * 8 + (lane & 7);
    const int kgB_add = (lane >> 3) & 1;

    float acc[8][4] = {};

    ldg_chunk(0);

    for (int c = 0; c < 8; c++) {
        sts_chunk();
        __syncthreads();
        if (c < 7) ldg_chunk(c + 1);

        #pragma unroll
        for (int ks = 0; ks < 4; ks++) {
            const int kgA = ks * 2 + kselA;
            const uint32_t aoff = (uint32_t)(rA * 128 + ((kgA ^ rx7A) << 4));
            uint32_t ahi[4], alo[4];
            LDSM4(ahi, sb + SM_AHI + aoff);
            LDSM4(alo, sb + SM_ALO + aoff);

            #pragma unroll
            for (int j = 0; j < 4; j++) {
                const int rB  = j * 16 + rB_loc;
                const int kgB = ks * 2 + kgB_add;
                const uint32_t boff = (uint32_t)(rB * 128 + ((kgB ^ (rB & 7)) << 4));
                uint32_t bhi[4], blo[4];
                LDSM4(bhi, sb + SM_WHI + boff);
                LDSM4(blo, sb + SM_WLO + boff);

                MMA16816(acc[2 * j],     ahi, bhi[0], bhi[1]);
                MMA16816(acc[2 * j],     ahi, blo[0], blo[1]);
                MMA16816(acc[2 * j],     alo, bhi[0], bhi[1]);
                MMA16816(acc[2 * j + 1], ahi, bhi[2], bhi[3]);
                MMA16816(acc[2 * j + 1], ahi, blo[2], blo[3]);
                MMA16816(acc[2 * j + 1], alo, bhi[2], bhi[3]);
            }
        }
        __syncthreads();
    }

    // Epilogue: store (+b1 for q) and accumulate per-row dot with w2/2.
    const int er = lane >> 2;
    const int ec = (lane & 3) * 2;
    float* d0 = dst + (size_t)(wid * 16 + er) * HID;
    float* d1 = dst + (size_t)(wid * 16 + er + 8) * HID;

    float wp[16];
    #pragma unroll
    for (int nf = 0; nf < 8; nf++) {
        float2 wv = *(const float2*)(W2 + m * HID + nf * 8 + ec);
        wp[2 * nf]     = 0.5f * wv.x;
        wp[2 * nf + 1] = 0.5f * wv.y;
    }

    float r0 = 0.f, r1 = 0.f;
    #pragma unroll
    for (int nf = 0; nf < 8; nf++) {
        float bx = 0.f, by = 0.f;
        if (is_q) {
            float2 bv = *(const float2*)(b1 + m * HID + nf * 8 + ec);
            bx = bv.x; by = bv.y;
        }
        float o00 = acc[nf][0] + bx, o01 = acc[nf][1] + by;
        float o10 = acc[nf][2] + bx, o11 = acc[nf][3] + by;
        *(float2*)(d0 + nf * 8 + ec) = make_float2(o00, o01);
        *(float2*)(d1 + nf * 8 + ec) = make_float2(o10, o11);
        r0 += o00 * wp[2 * nf] + o01 * wp[2 * nf + 1];
        r1 += o10 * wp[2 * nf] + o11 * wp[2 * nf + 1];
    }
    r0 += __shfl_xor_sync(0xFFFFFFFF, r0, 1);
    r0 += __shfl_xor_sync(0xFFFFFFFF, r0, 2);
    r1 += __shfl_xor_sync(0xFFFFFFFF, r1, 1);
    r1 += __shfl_xor_sync(0xFFFFFFFF, r1, 2);
    if ((lane & 3) == 0) {
        rs_dst[wid * 16 + er]     = r0;
        rs_dst[wid * 16 + er + 8] = r1;
    }
}

// ===========================================================================
// Kernel 2: fused |.|-combine + ensemble stats using precomputed rowsums.
//   o[m,q,p] = rsq[m,q] + rsp[m,p] + sum_h |x+y|*w' + b2[m]   (w' = w2/2)
// Tile: 64q x 32p, 128 threads, 4x4 outputs/thread. grid (32,8) = 256 blocks.
// Inner pair: add.f32x2 + and.b64 + fma.f32x2  (2 fma-pipe + 2 alu-pipe).
// ===========================================================================
#define BQ 64
#define BP 32
#define BUF_FLOATS ((BQ + BP) * HID)              // 6144 floats = 24 KB
#define RS_PER_M   (BQ + BP)                      // 96
#define SMEM_FLOATS (2 * BUF_FLOATS + NM * HID + NM * RS_PER_M + 8)
#define SMEM_BYTES  (SMEM_FLOATS * 4)

#define ABS_FMA2(acc, x2, y2, w2)                                     \
    asm("{\n\t"                                                       \
        ".reg .b64 s;\n\t"                                            \
        "add.rn.f32x2 s, %1, %2;\n\t"                                 \
        "and.b64 s, s, 0x7FFFFFFF7FFFFFFF;\n\t"                       \
        "fma.rn.f32x2 %0, s, %3, %0;\n\t"                             \
        "}"                                                           \
        : "+l"(acc) : "l"(x2), "l"(y2), "l"(w2))

__device__ __forceinline__ void cpa16(void* smem_ptr, const void* gptr) {
    uint32_t s = (uint32_t)__cvta_generic_to_shared(smem_ptr);
    asm volatile("cp.async.cg.shared.global [%0], [%1], 16;" :: "r"(s), "l"(gptr));
}

__global__ __launch_bounds__(128) void final_kernel(
    const float* __restrict__ W2, const float* __restrict__ b2,
    float* __restrict__ out)
{
    extern __shared__ float smem_f[];
    float* s_w2 = smem_f + 2 * BUF_FLOATS;     // [NM][HID], prescaled 0.5
    float* s_rs = s_w2 + NM * HID;             // [NM][96]: 64 q then 32 p
    float* s_b2 = s_rs + NM * RS_PER_M;

    const int tid = threadIdx.x;               // 0..127
    const int q0  = blockIdx.x * BQ;
    const int p0  = blockIdx.y * BP;
    const int tyq = tid >> 3;                  // 0..15 -> q rows tyq*4..+3
    const int txp = tid & 7;                   // 0..7  -> p rows txp*4..+3

    for (int i = tid; i < NM * HID; i += 128) s_w2[i] = 0.5f * W2[i];
    // rowsums for this tile: 5 m x (64 q + 32 p) = 480 floats
    for (int i = tid; i < NM * RS_PER_M; i += 128) {
        int m = i / RS_PER_M;
        int r = i % RS_PER_M;
        s_rs[i] = (r < BQ) ? g_rsq[m * N_Q + q0 + r]
                           : g_rsp[m * N_P + p0 + (r - BQ)];
    }
    if (tid < NM) s_b2[tid] = b2[tid];

    // stage one model's tiles: x 64x16 f4 + y 32x16 f4 = 1536 -> 12/thread
    auto stage = [&](int m, int b) {
        float* base = smem_f + b * BUF_FLOATS;
        #pragma unroll
        for (int k = 0; k < 12; k++) {
            int idx = tid + k * 128;
            const float* g;
            float* s;
            if (idx < 1024) {
                int row = idx >> 4;
                int c4  = idx & 15;
                int sc  = ((c4 ^ (row >> 2)) & 15) * 4;
                g = g_hqs + ((size_t)(m * N_Q + q0 + row)) * HID + c4 * 4;
                s = base + row * HID + sc;
            } else {
                int t   = idx - 1024;
                int row = t >> 4;
                int c4  = t & 15;
                int sc  = ((c4 ^ (row >> 2)) & 15) * 4;
                g = g_hps + ((size_t)(m * N_P + p0 + row)) * HID + c4 * 4;
                s = base + (BQ + row) * HID + sc;
            }
            cpa16(s, g);
        }
        asm volatile("cp.async.commit_group;");
    };

    stage(0, 0);
    stage(1, 1);

    float sum[4][4] = {};
    float sq [4][4] = {};

    for (int m = 0; m < NM; m++) {
        if (m < NM - 1) {
            asm volatile("cp.async.wait_group 1;");
        } else {
            asm volatile("cp.async.wait_group 0;");
        }
        __syncthreads();

        const float* bx   = smem_f + (m & 1) * BUF_FLOATS;
        const float* xrow = bx + (tyq * 4) * HID;
        const float* yrow = bx + (BQ + txp * 4) * HID;
        const float* wrow = s_w2 + m * HID;

        unsigned long long acc[4][4] = {};

        #pragma unroll 4
        for (int c4 = 0; c4 < 16; c4++) {
            int cx = ((c4 ^ tyq) & 15) * 4;
            int cy = ((c4 ^ txp) & 15) * 4;
            ulonglong2 X[4], Y[4];
            #pragma unroll
            for (int i = 0; i < 4; i++)
                X[i] = *(const ulonglong2*)(xrow + i * HID + cx);
            #pragma unroll
            for (int j = 0; j < 4; j++)
                Y[j] = *(const ulonglong2*)(yrow + j * HID + cy);
            ulonglong2 Wv = *(const ulonglong2*)(wrow + c4 * 4);

            #pragma unroll
            for (int i = 0; i < 4; i++)
                #pragma unroll
                for (int j = 0; j < 4; j++) {
                    ABS_FMA2(acc[i][j], X[i].x, Y[j].x, Wv.x);
                    ABS_FMA2(acc[i][j], X[i].y, Y[j].y, Wv.y);
                }
        }

        float bb = s_b2[m];
        float rsx[4], rsy[4];
        #pragma unroll
        for (int i = 0; i < 4; i++) rsx[i] = s_rs[m * RS_PER_M + tyq * 4 + i] + bb;
        #pragma unroll
        for (int j = 0; j < 4; j++) rsy[j] = s_rs[m * RS_PER_M + BQ + txp * 4 + j];

        #pragma unroll
        for (int i = 0; i < 4; i++)
            #pragma unroll
            for (int j = 0; j < 4; j++) {
                unsigned long long a = acc[i][j];
                float lo = __uint_as_float((unsigned)(a & 0xFFFFFFFFull));
                float hi = __uint_as_float((unsigned)(a >> 32));
                float o  = lo + hi + rsx[i] + rsy[j];
                sum[i][j] += o;
                sq [i][j] += o * o;
            }

        __syncthreads();
        if (m + 2 < NM) stage(m + 2, m & 1);
    }

    #pragma unroll
    for (int i = 0; i < 4; i++) {
        float4 r4;
        float* rp = (float*)&r4;
        #pragma unroll
        for (int j = 0; j < 4; j++) {
            float mean = sum[i][j] * 0.2f;
            float var  = fmaxf(sq[i][j] - 5.0f * mean * mean, 0.0f) * 0.25f; // ddof=1
            rp[j] = mean * expf(-sqrtf(var));
        }
        int q = q0 + tyq * 4 + i;
        *(float4*)(out + (size_t)q * N_P + p0 + txp * 4) = r4;
    }
}

// ---------------------------------------------------------------------------
extern "C" void kernel_launch(void* const* d_in, const int* in_sizes, int n_in,
                              void* d_out, int out_size)
{
    const float* Q  = (const float*)d_in[0];
    const float* P  = (const float*)d_in[1];
    const float* W1 = (const float*)d_in[2];
    const float* b1 = (const float*)d_in[3];
    const float* W2 = (const float*)d_in[4];
    const float* b2 = (const float*)d_in[5];
    float* out = (float*)d_out;

    dim3 g1(N_Q / 64 + N_P / 64, NM);             // (36, 5) = 180 blocks
    gemm_mma_kernel<<<g1, 128>>>(Q, P, W1, b1, W2);

    cudaFuncSetAttribute(final_kernel,
                         cudaFuncAttributeMaxDynamicSharedMemorySize, SMEM_BYTES);
    dim3 g3(N_Q / BQ, N_P / BP);                  // (32, 8) = 256 blocks
    final_kernel<<<g3, 128, SMEM_BYTES>>>(W2, b2, out);
}